// round 17
// baseline (speedup 1.0000x reference)
#include <cuda_runtime.h>
#include <cuda_bf16.h>
#include <cstdint>

// LSTM_WP — fused bf16 mma.sync, 4 batch-groups rotated PER-SMSP-SLOT.
// Single CTA, 512 threads (16 warps). Warp w owns units u0 = w*8+gid (all 4
// gates, 32 rows) as bf16x2 register frags. N=32 batches in 4 groups of 8.
// KEY (R12): group order g = ((wid>>2)+j)&3 -- the 4 warps sharing one SMSP
// are always in 4 DIFFERENT groups, so per-SMSP MUFU/FMA/LSU overlap the
// tensor pipe instead of phase-marching in lockstep (R11 bug: rotation by wid
// made warps {0,4,8,12} of SMSP0 process the same group simultaneously).
// D stays in registers (warp's rows = all 4 gates of its own units).
// Per group: phase-tracked shared::cta mbarrier (16 arrivals, parity per step).
// h bf16 double-buffered per group; x fp32; final h fp32 for exact fc head.

#define TT 128
#define NTHR 512

// dynamic smem (bytes)
#define OFF_H   0            // 4 groups x 2 bufs x 2048
#define H_GRP   4096
#define OFF_X   16384        // 128 t x 33 floats = 16896
#define OFF_HF  33280        // 128 u x 32 n x 4 = 16384
#define OFF_BAR 49664        // 4 mbarriers
#define SMEM_REQ 49728

__device__ __forceinline__ uint32_t smem_u32(const void* p) {
    uint32_t a;
    asm("{ .reg .u64 t; cvta.to.shared.u64 t, %1; cvt.u32.u64 %0, t; }" : "=r"(a) : "l"(p));
    return a;
}
__device__ __forceinline__ uint32_t pk_bf16(float lo, float hi) {
    uint32_t r; asm("cvt.rn.bf16x2.f32 %0, %1, %2;" : "=r"(r) : "f"(hi), "f"(lo)); return r;
}
__device__ __forceinline__ float tanh_ap(float x) {
    float y; asm("tanh.approx.f32 %0, %1;" : "=f"(y) : "f"(x)); return y;
}
__device__ __forceinline__ float sig_ap(float x) { return fmaf(tanh_ap(0.5f * x), 0.5f, 0.5f); }

#define MBAR_INIT(a, n) \
    asm volatile("mbarrier.init.shared.b64 [%0], %1;" :: "r"(a), "r"((uint32_t)(n)) : "memory")
#define MBAR_ARRIVE(a) \
    asm volatile("mbarrier.arrive.shared.b64 _, [%0];" :: "r"(a) : "memory")

__device__ __forceinline__ void mbar_wait(uint32_t a, uint32_t par) {
    uint32_t done;
    do {
        asm volatile("{ .reg .pred p;"
                     " mbarrier.try_wait.parity.shared.b64 p, [%1], %2, 0x989680;"
                     " selp.b32 %0,1,0,p; }"
                     : "=r"(done) : "r"(a), "r"(par) : "memory");
    } while (!done);
}

#define MMA_BF16(d, a, b0, b1) \
    asm volatile("mma.sync.aligned.m16n8k16.row.col.f32.bf16.bf16.f32 " \
                 "{%0,%1,%2,%3}, {%4,%5,%6,%7}, {%8,%9}, {%0,%1,%2,%3};" \
                 : "+f"((d)[0]), "+f"((d)[1]), "+f"((d)[2]), "+f"((d)[3]) \
                 : "r"((a)[0]), "r"((a)[1]), "r"((a)[2]), "r"((a)[3]), \
                   "r"(b0), "r"(b1))

__global__ __launch_bounds__(NTHR, 1)
void lstm_rot2(const float* __restrict__ x,
               const float* __restrict__ W_ih,
               const float* __restrict__ W_hh,
               const float* __restrict__ b_ih,
               const float* __restrict__ b_hh,
               const float* __restrict__ fc_W,
               const float* __restrict__ fc_b,
               float* __restrict__ out)
{
    extern __shared__ char sm[];
    const uint32_t sb = smem_u32(sm);
    const int tid = threadIdx.x, wid = tid >> 5, lane = tid & 31;
    const int gid = lane >> 2, tig = lane & 3;
    const int b0g = blockIdx.x * 32;

    // ---- init: mbarriers, x fp32 [t][33], zero h (both bufs, all groups) ----
    if (tid == 0) {
        #pragma unroll
        for (int g = 0; g < 4; g++) MBAR_INIT(sb + OFF_BAR + g * 8, 16);
    }
    float* xs = (float*)(sm + OFF_X);
    for (int i = tid; i < 32 * TT; i += NTHR) {
        int n = i >> 7, t = i & 127;
        xs[t * 33 + n] = x[(size_t)(b0g + n) * TT + t];
    }
    {
        uint32_t* hz = (uint32_t*)(sm + OFF_H);
        for (int i = tid; i < 4096; i += NTHR) hz[i] = 0u;
    }

    // ---- W fragments in registers (bf16x2, 64 regs) ----
    const int u0 = wid * 8 + gid;                 // unit 0..127
    uint32_t wreg[2][8][4];
    #pragma unroll
    for (int mt = 0; mt < 2; mt++) {
        const float* rl = W_hh + (size_t)((2 * mt)     * 128 + u0) * 128;
        const float* rh = W_hh + (size_t)((2 * mt + 1) * 128 + u0) * 128;
        #pragma unroll
        for (int kt = 0; kt < 8; kt++) {
            int k0 = kt * 16 + tig * 2;
            wreg[mt][kt][0] = pk_bf16(__ldg(rl + k0),     __ldg(rl + k0 + 1));
            wreg[mt][kt][1] = pk_bf16(__ldg(rh + k0),     __ldg(rh + k0 + 1));
            wreg[mt][kt][2] = pk_bf16(__ldg(rl + k0 + 8), __ldg(rl + k0 + 9));
            wreg[mt][kt][3] = pk_bf16(__ldg(rh + k0 + 8), __ldg(rh + k0 + 9));
        }
    }
    float wi[4], bsv[4];
    #pragma unroll
    for (int g4 = 0; g4 < 4; g4++) {
        int row = g4 * 128 + u0;
        wi[g4]  = W_ih[row];
        bsv[g4] = b_ih[row] + b_hh[row];
    }

    const uint32_t lane_rd = (uint32_t)(gid * 32 + tig * 8);          // B-frag lane off
    const int upair = u0 & ~1;
    const uint32_t wordoff = (uint32_t)((upair >> 4) * 256 + ((upair >> 1) & 3) * 8
                                        + ((upair >> 3) & 1) * 4);
    const bool even = ((gid & 1) == 0);
    float* hf = (float*)(sm + OFF_HF);

    // per-j precomputed group constants (g fixed per j across all t)
    const int grot = wid >> 2;                    // SMSP-slot rotation
    uint32_t gbar[4], gbase[4];
    int gvec[4];
    #pragma unroll
    for (int j = 0; j < 4; j++) {
        const int g = (grot + j) & 3;
        gvec[j]  = g;
        gbar[j]  = sb + OFF_BAR + (uint32_t)g * 8;
        gbase[j] = sb + OFF_H + (uint32_t)g * H_GRP;
    }

    float cst[4][2];
    #pragma unroll
    for (int g = 0; g < 4; g++) { cst[g][0] = 0.f; cst[g][1] = 0.f; }

    __syncthreads();   // x + zero-h + mbar init visible

    for (int t = 0; t < TT; t++) {
        const uint32_t rbo = (uint32_t)(t & 1) * 2048;
        const uint32_t wbo = (uint32_t)((t + 1) & 1) * 2048;
        const float* xrow = xs + t * 33;
        #pragma unroll
        for (int j = 0; j < 4; j++) {
            const int g = gvec[j];
            // wait: all 16 warps published h_g(t) (phase t-1); t=0 reads zeros
            if (t > 0) mbar_wait(gbar[j], (uint32_t)((t - 1) & 1));

            // ---- MMA: 2 mt x (two 4-deep k chains) ----
            float acc[2][2][4];
            #pragma unroll
            for (int mt = 0; mt < 2; mt++)
                #pragma unroll
                for (int kh = 0; kh < 2; kh++)
                    #pragma unroll
                    for (int r = 0; r < 4; r++) acc[mt][kh][r] = 0.f;
            const uint32_t hb = gbase[j] + rbo + lane_rd;
            #pragma unroll
            for (int kt = 0; kt < 8; kt++) {
                uint32_t b0, b1;
                asm volatile("ld.shared.v2.b32 {%0,%1}, [%2];"
                             : "=r"(b0), "=r"(b1) : "r"(hb + (uint32_t)(kt * 256)));
                MMA_BF16(acc[0][kt >> 2], wreg[0][kt], b0, b1);
                MMA_BF16(acc[1][kt >> 2], wreg[1][kt], b0, b1);
            }

            // ---- epilogue (warp-local: acc holds all 4 gates of unit u0) ----
            const uint32_t wL = gbase[j] + wbo + wordoff;
            #pragma unroll
            for (int e = 0; e < 2; e++) {
                const int n = tig * 2 + e;
                const float xv = xrow[g * 8 + n];
                const float pi = (acc[0][0][e]     + acc[0][1][e])     + fmaf(xv, wi[0], bsv[0]);
                const float pf = (acc[0][0][2 + e] + acc[0][1][2 + e]) + fmaf(xv, wi[1], bsv[1]);
                const float pg = (acc[1][0][e]     + acc[1][1][e])     + fmaf(xv, wi[2], bsv[2]);
                const float po = (acc[1][0][2 + e] + acc[1][1][2 + e]) + fmaf(xv, wi[3], bsv[3]);
                const float gi = sig_ap(pi), gf = sig_ap(pf);
                const float gg = tanh_ap(pg), go = sig_ap(po);
                const float cn = fmaf(gf, cst[g][e], gi * gg);
                cst[g][e] = cn;
                const float hv = go * tanh_ap(cn);
                const float hp = __shfl_xor_sync(0xffffffffu, hv, 4);
                if (even) {
                    const uint32_t w = pk_bf16(hv, hp);
                    asm volatile("st.shared.b32 [%0], %1;"
                                 :: "r"(wL + (uint32_t)n * 32), "r"(w) : "memory");
                }
                if (t == TT - 1) hf[u0 * 32 + g * 8 + n] = hv;
            }
            __syncwarp();
            if (lane == 0) MBAR_ARRIVE(gbar[j]);
        }
    }

    __syncthreads();   // hf complete
    // ---- fc head on fp32 final h ----
    if (wid == 0) {
        const int n = lane;
        float s = fc_b[0];
        #pragma unroll 8
        for (int u = 0; u < 128; u++)
            s = fmaf(hf[u * 32 + n], __ldg(fc_W + u), s);
        out[b0g + n] = s;
    }
}

extern "C" void kernel_launch(void* const* d_in, const int* in_sizes, int n_in,
                              void* d_out, int out_size)
{
    const float* x    = (const float*)d_in[0];
    const float* W_ih = (const float*)d_in[1];
    const float* W_hh = (const float*)d_in[2];
    const float* b_ih = (const float*)d_in[3];
    const float* b_hh = (const float*)d_in[4];
    const float* fc_W = (const float*)d_in[5];
    const float* fc_b = (const float*)d_in[6];

    const int B = in_sizes[0] / TT;    // 4096
    const int grid = B / 32;           // 128 CTAs, one wave

    cudaFuncSetAttribute(lstm_rot2, cudaFuncAttributeMaxDynamicSharedMemorySize, SMEM_REQ);
    lstm_rot2<<<grid, NTHR, SMEM_REQ>>>(x, W_ih, W_hh, b_ih, b_hh, fc_W, fc_b, (float*)d_out);
}